// round 1
// baseline (speedup 1.0000x reference)
#include <cuda_runtime.h>

#define NB    65536
#define DIM   256
#define NK    1024

#define BM 128
#define BN 128
#define BK 64
#define TM 8
#define TN 8
#define NTHREADS 256

// Scratch (no cudaMalloc allowed): codebook transposed [K][DIM], code norms, per-CTA diff partials
__device__ float g_embedT[NK * DIM];
__device__ float g_esq[NK];
__device__ float g_partials[NB / BM];

// ---------------------------------------------------------------------------
// Prep: transpose embed [DIM][K] -> embedT [K][DIM]
// ---------------------------------------------------------------------------
__global__ void k_prep(const float* __restrict__ embed) {
    int idx = blockIdx.x * blockDim.x + threadIdx.x;
    if (idx < DIM * NK) {
        int d = idx >> 10;         // row in embed (dim)
        int k = idx & (NK - 1);    // col in embed (code)
        g_embedT[k * DIM + d] = embed[idx];
    }
}

// e_sq[k] = ||e_k||^2   (one warp per code)
__global__ void k_esq() {
    int k = blockIdx.x * (blockDim.x >> 5) + (threadIdx.x >> 5);
    int lane = threadIdx.x & 31;
    const float* row = g_embedT + k * DIM;
    float s = 0.f;
    for (int d = lane; d < DIM; d += 32) { float v = row[d]; s += v * v; }
    #pragma unroll
    for (int o = 16; o; o >>= 1) s += __shfl_xor_sync(0xffffffffu, s, o);
    if (lane == 0) g_esq[k] = s;
}

// ---------------------------------------------------------------------------
// f32x2 packed-FMA helpers (Blackwell FFMA2: 2 fp32 FMAs per instruction slot)
// ---------------------------------------------------------------------------
__device__ __forceinline__ unsigned long long ffma2(unsigned long long a,
                                                    unsigned long long b,
                                                    unsigned long long c) {
    unsigned long long d;
    asm("fma.rn.f32x2 %0, %1, %2, %3;" : "=l"(d) : "l"(a), "l"(b), "l"(c));
    return d;
}
__device__ __forceinline__ unsigned long long bcast2(float v) {
    unsigned long long d;
    asm("mov.b64 %0, {%1, %1};" : "=l"(d) : "f"(v));
    return d;
}
__device__ __forceinline__ float2 unpack2(unsigned long long v) {
    float2 r;
    asm("mov.b64 {%0, %1}, %2;" : "=f"(r.x), "=f"(r.y) : "l"(v));
    return r;
}

// ---------------------------------------------------------------------------
// Main: fused GEMM + argmin + gather + diff-partial
//   score(b,k) = e_sq[k] - 2 * x_b . e_k   (x^2 term is row-constant)
// ---------------------------------------------------------------------------
__global__ __launch_bounds__(NTHREADS, 1) void k_main(const float* __restrict__ x,
                                                      float* __restrict__ out) {
    extern __shared__ float smem[];
    float* x_s = smem;                       // [BM][DIM]  128KB, resident
    float* e_s = smem + BM * DIM;            // [BK][BN]   32KB  (k-major, codes contiguous)
    // reduction scratch reuses the e_s region after the mainloop
    float* redv = e_s;                       // [BM][16]
    int*   redi = (int*)(e_s + BM * 16);     // [BM][16]
    int*   ind_s = (int*)(e_s + BM * 32);    // [BM]

    const int row0 = blockIdx.x * BM;
    const int tid = threadIdx.x;

    // load x tile once (coalesced float4)
    const float4* xg = (const float4*)(x + (size_t)row0 * DIM);
    float4* xs4 = (float4*)x_s;
    for (int i = tid; i < BM * DIM / 4; i += NTHREADS) xs4[i] = xg[i];

    const int ty = tid >> 4;
    const int tx = tid & 15;
    const int rbase = ty * TM;    // 8 rows
    const int cbase = tx * TN;    // 8 codes (4 f32x2 pairs)

    float bestv[TM];
    int   besti[TM];
    #pragma unroll
    for (int i = 0; i < TM; i++) { bestv[i] = 3.4e38f; besti[i] = 0; }

    for (int ct = 0; ct < NK / BN; ++ct) {
        unsigned long long acc[TM][TN / 2];
        #pragma unroll
        for (int i = 0; i < TM; i++)
            #pragma unroll
            for (int j = 0; j < TN / 2; j++) acc[i][j] = 0ull;

        for (int kc = 0; kc < DIM / BK; ++kc) {
            __syncthreads();
            // stage e_s[k][c] = embedT[ct*BN + c][kc*BK + k]  (transpose on store)
            for (int i = tid; i < BN * BK / 4; i += NTHREADS) {
                int c  = i >> 4;      // 0..127
                int k4 = i & 15;      // 0..15 (groups of 4 k)
                float4 v = *(const float4*)&g_embedT[(ct * BN + c) * DIM + kc * BK + k4 * 4];
                e_s[(k4 * 4 + 0) * BN + c] = v.x;
                e_s[(k4 * 4 + 1) * BN + c] = v.y;
                e_s[(k4 * 4 + 2) * BN + c] = v.z;
                e_s[(k4 * 4 + 3) * BN + c] = v.w;
            }
            __syncthreads();

            #pragma unroll 4
            for (int k = 0; k < BK; k += 4) {
                float4 a4[TM];
                #pragma unroll
                for (int i = 0; i < TM; i++)
                    a4[i] = *(const float4*)&x_s[(rbase + i) * DIM + kc * BK + k];
                #pragma unroll
                for (int kk = 0; kk < 4; kk++) {
                    const unsigned long long* bsrc =
                        (const unsigned long long*)&e_s[(k + kk) * BN + cbase];
                    unsigned long long b[TN / 2];
                    #pragma unroll
                    for (int j = 0; j < TN / 2; j++) b[j] = bsrc[j];
                    #pragma unroll
                    for (int i = 0; i < TM; i++) {
                        float av = (kk == 0) ? a4[i].x : (kk == 1) ? a4[i].y
                                 : (kk == 2) ? a4[i].z : a4[i].w;
                        unsigned long long aa = bcast2(av);
                        #pragma unroll
                        for (int j = 0; j < TN / 2; j++)
                            acc[i][j] = ffma2(aa, b[j], acc[i][j]);
                    }
                }
            }
        }

        // fold this code tile into the running argmin (ascending code order ->
        // strict < keeps the first/lowest index on exact ties, like jnp.argmin)
        #pragma unroll
        for (int j = 0; j < TN / 2; j++) {
            int c0 = ct * BN + cbase + 2 * j;
            float es0 = g_esq[c0];
            float es1 = g_esq[c0 + 1];
            #pragma unroll
            for (int i = 0; i < TM; i++) {
                float2 s = unpack2(acc[i][j]);
                float d0 = es0 - 2.f * s.x;
                float d1 = es1 - 2.f * s.y;
                if (d0 < bestv[i]) { bestv[i] = d0; besti[i] = c0; }
                if (d1 < bestv[i]) { bestv[i] = d1; besti[i] = c0 + 1; }
            }
        }
    }

    // cross-thread (over tx groups) argmin reduce per row
    __syncthreads();
    #pragma unroll
    for (int i = 0; i < TM; i++) {
        redv[(rbase + i) * 16 + tx] = bestv[i];
        redi[(rbase + i) * 16 + tx] = besti[i];
    }
    __syncthreads();
    if (tid < BM) {
        float bv = redv[tid * 16];
        int   bi = redi[tid * 16];
        #pragma unroll
        for (int t = 1; t < 16; t++) {
            float v = redv[tid * 16 + t];
            int  ii = redi[tid * 16 + t];
            if (v < bv || (v == bv && ii < bi)) { bv = v; bi = ii; }
        }
        ind_s[tid] = bi;
        out[(size_t)NB * DIM + 1 + row0 + tid] = (float)bi;   // embed_ind output
    }
    __syncthreads();

    // epilogue: gather quantize rows (L2-resident codebook), write out,
    // accumulate diff partial against SMEM-resident x
    float dsum = 0.f;
    for (int i = tid; i < BM * DIM / 4; i += NTHREADS) {
        int r  = i >> 6;
        int d4 = i & 63;
        float4 q  = *(const float4*)&g_embedT[ind_s[r] * DIM + d4 * 4];
        float4 xv = xs4[i];
        *(float4*)&out[((size_t)(row0 + r)) * DIM + d4 * 4] = q;
        float a0 = q.x - xv.x, a1 = q.y - xv.y, a2 = q.z - xv.z, a3 = q.w - xv.w;
        dsum += a0 * a0 + a1 * a1 + a2 * a2 + a3 * a3;
    }
    __shared__ float warp_sums[NTHREADS / 32];
    #pragma unroll
    for (int o = 16; o; o >>= 1) dsum += __shfl_xor_sync(0xffffffffu, dsum, o);
    if ((tid & 31) == 0) warp_sums[tid >> 5] = dsum;
    __syncthreads();
    if (tid == 0) {
        float t = 0.f;
        #pragma unroll
        for (int w = 0; w < NTHREADS / 32; w++) t += warp_sums[w];
        g_partials[blockIdx.x] = t;   // deterministic (no atomics)
    }
}

// finalize diff = sum(partials) / (NB*DIM)
__global__ void k_final(float* __restrict__ out) {
    __shared__ float ws[16];
    int tid = threadIdx.x;                 // 512 threads, one per partial
    float s = g_partials[tid];
    #pragma unroll
    for (int o = 16; o; o >>= 1) s += __shfl_xor_sync(0xffffffffu, s, o);
    if ((tid & 31) == 0) ws[tid >> 5] = s;
    __syncthreads();
    if (tid == 0) {
        float t = 0.f;
        #pragma unroll
        for (int w = 0; w < 16; w++) t += ws[w];
        out[(size_t)NB * DIM] = t / (float)((size_t)NB * DIM);
    }
}

extern "C" void kernel_launch(void* const* d_in, const int* in_sizes, int n_in,
                              void* d_out, int out_size) {
    const float* x     = (const float*)d_in[0];
    const float* embed = (const float*)d_in[1];
    float* out = (float*)d_out;

    const int smem_bytes = (BM * DIM + BK * BN) * 4;   // 160 KB
    cudaFuncSetAttribute(k_main, cudaFuncAttributeMaxDynamicSharedMemorySize, smem_bytes);

    k_prep<<<(DIM * NK + 255) / 256, 256>>>(embed);
    k_esq<<<NK / 8, 256>>>();
    k_main<<<NB / BM, NTHREADS, smem_bytes>>>(x, out);
    k_final<<<1, NB / BM>>>(out);
}